// round 2
// baseline (speedup 1.0000x reference)
#include <cuda_runtime.h>
#include <cuda_bf16.h>

// 3D RoPE apply:
//   x: (1, S, N=16, D=128) fp32, S = f*h*w
//   freqs_cos/sin: (1024, 64) fp32, cols [0,22)=F table, [22,43)=H, [43,64)=W
//   For seq pos s -> (fi, hi, wi); channel pair c in [0,64):
//     angle row = fi if c<22 else hi if c<43 else wi
//   out pair: (xr*cos - xi*sin, xr*sin + xi*cos)
//
// HBM-bound: 268 MB in + 268 MB out. One block per s, 512 threads,
// one float4 (2 pairs) per thread; 64 cos + 64 sin staged in smem.

#define NHEADS 16
#define DDIM   128
#define CPAIRS 64            // D/2
#define VEC_PER_S (NHEADS * DDIM / 4)   // 512 float4 per seq position

__global__ __launch_bounds__(VEC_PER_S, 4)
void rope3d_kernel(const float4* __restrict__ x,
                   const float*  __restrict__ fcos,
                   const float*  __restrict__ fsin,
                   const int*    __restrict__ p_h,
                   const int*    __restrict__ p_w,
                   float4*       __restrict__ out)
{
    const int s = blockIdx.x;
    const int t = threadIdx.x;

    __shared__ float sc[CPAIRS];
    __shared__ float ss[CPAIRS];

    if (t < CPAIRS) {
        const int h = *p_h;
        const int w = *p_w;
        const int hw  = h * w;
        const int fi  = s / hw;
        const int rem = s - fi * hw;
        const int hi  = rem / w;
        const int wi  = rem - hi * w;
        const int pos = (t < 22) ? fi : ((t < 43) ? hi : wi);
        sc[t] = __ldg(&fcos[pos * CPAIRS + t]);
        ss[t] = __ldg(&fsin[pos * CPAIRS + t]);
    }
    __syncthreads();

    const int idx = s * VEC_PER_S + t;      // coalesced across the block
    const int j   = (t & 31) << 1;          // first channel-pair index of this float4

    float4 v = x[idx];

    const float c0 = sc[j],     s0 = ss[j];
    const float c1 = sc[j + 1], s1 = ss[j + 1];

    float4 o;
    o.x = fmaf(v.x, c0, -v.y * s0);
    o.y = fmaf(v.x, s0,  v.y * c0);
    o.z = fmaf(v.z, c1, -v.w * s1);
    o.w = fmaf(v.z, s1,  v.w * c1);

    out[idx] = o;
}

extern "C" void kernel_launch(void* const* d_in, const int* in_sizes, int n_in,
                              void* d_out, int out_size)
{
    const float4* x    = (const float4*)d_in[0];
    const float*  fcos = (const float*)d_in[1];
    const float*  fsin = (const float*)d_in[2];
    // d_in[3] = f (unused on device), d_in[4] = h, d_in[5] = w
    const int* p_h = (const int*)d_in[4];
    const int* p_w = (const int*)d_in[5];
    float4* out = (float4*)d_out;

    const int s_total = in_sizes[0] / (NHEADS * DDIM);   // 32760

    rope3d_kernel<<<s_total, VEC_PER_S>>>(x, fcos, fsin, p_h, p_w, out);
}

// round 4
// speedup vs baseline: 1.0538x; 1.0538x over previous
#include <cuda_runtime.h>
#include <cuda_bf16.h>

// 3D RoPE apply:
//   x: (1, S, N=16, D=128) fp32, S = f*h*w (= 32760)
//   freqs_cos/sin: (1024, 64) fp32, cols [0,22)=F, [22,43)=H, [43,64)=W
//   seq pos s -> (fi, hi, wi); pair c: row = fi (c<22) | hi (c<43) | wi
//   out pair: (xr*cos - xi*sin, xr*sin + xi*cos)
//
// R2: 4 seq positions per block; each thread front-batches 4 independent
// LDG.128 (MLP_p1=4) to push DRAM toward the HBM ceiling.

#define NHEADS 16
#define DDIM   128
#define CPAIRS 64                        // D/2
#define VEC_PER_S (NHEADS * DDIM / 4)    // 512 float4 per seq position
#define SPB 4                            // seq positions per block
#define THREADS VEC_PER_S

__global__ __launch_bounds__(THREADS, 3)
void rope3d_kernel(const float4* __restrict__ x,
                   const float*  __restrict__ fcos,
                   const float*  __restrict__ fsin,
                   const int*    __restrict__ p_h,
                   const int*    __restrict__ p_w,
                   float4*       __restrict__ out,
                   int s_total)
{
    const int s0 = blockIdx.x * SPB;
    const int t  = threadIdx.x;

    __shared__ float sc[SPB][CPAIRS];
    __shared__ float ss[SPB][CPAIRS];

    // Stage SPB rows of cos/sin (SPB*64 = 256 staging threads)
    if (t < SPB * CPAIRS) {
        const int k = t >> 6;        // which seq position in this block
        const int c = t & 63;        // channel pair
        const int s = s0 + k;
        if (s < s_total) {
            const int h  = *p_h;
            const int w  = *p_w;
            const int hw = h * w;
            const int fi  = s / hw;
            const int rem = s - fi * hw;
            const int hi  = rem / w;
            const int wi  = rem - hi * w;
            const int pos = (c < 22) ? fi : ((c < 43) ? hi : wi);
            sc[k][c] = __ldg(&fcos[pos * CPAIRS + c]);
            ss[k][c] = __ldg(&fsin[pos * CPAIRS + c]);
        }
    }
    __syncthreads();

    const int j = (t & 31) << 1;     // first channel-pair index of this float4

    // Front-batch the 4 independent global loads (MLP = 4)
    float4 v[SPB];
    const int base = s0 * VEC_PER_S + t;
#pragma unroll
    for (int k = 0; k < SPB; ++k) {
        if (s0 + k < s_total) v[k] = x[base + k * VEC_PER_S];
    }

#pragma unroll
    for (int k = 0; k < SPB; ++k) {
        if (s0 + k >= s_total) break;
        const float c0 = sc[k][j],     sn0 = ss[k][j];
        const float c1 = sc[k][j + 1], sn1 = ss[k][j + 1];
        float4 o;
        o.x = fmaf(v[k].x, c0, -v[k].y * sn0);
        o.y = fmaf(v[k].x, sn0,  v[k].y * c0);
        o.z = fmaf(v[k].z, c1, -v[k].w * sn1);
        o.w = fmaf(v[k].z, sn1,  v[k].w * c1);
        out[base + k * VEC_PER_S] = o;
    }
}

extern "C" void kernel_launch(void* const* d_in, const int* in_sizes, int n_in,
                              void* d_out, int out_size)
{
    const float4* x    = (const float4*)d_in[0];
    const float*  fcos = (const float*)d_in[1];
    const float*  fsin = (const float*)d_in[2];
    const int* p_h = (const int*)d_in[4];
    const int* p_w = (const int*)d_in[5];
    float4* out = (float4*)d_out;

    const int s_total = in_sizes[0] / (NHEADS * DDIM);   // 32760
    const int blocks  = (s_total + SPB - 1) / SPB;

    rope3d_kernel<<<blocks, THREADS>>>(x, fcos, fsin, p_h, p_w, out, s_total);
}